// round 1
// baseline (speedup 1.0000x reference)
#include <cuda_runtime.h>
#include <cstdint>

// ROI max pool, reference semantics:
//   ro = r >> 1; amin = max(a-ro, 0); amax = a+ro; if (amax > LIM) amax = LIM-1;
//   bin i: [amin + (i*len)/8, amin + ((i+1)*len+7)/8)
//   empty bin -> -inf
// feature_map: (C=256, H=64, W=64) f32, W contiguous.
// out: (N, C, 8, 8) f32.

namespace {
constexpr int Cdim = 256;
constexpr int Hdim = 64;
constexpr int Wdim = 64;
constexpr int PLANE = Hdim * Wdim;  // 4096
}

__global__ __launch_bounds__(256)
void roi_pool_kernel(const float* __restrict__ fm,
                     const int4* __restrict__ rois,
                     float* __restrict__ out)
{
    const int n    = blockIdx.x;
    const int tid  = threadIdx.x;
    const int warp = tid >> 5;
    const int lane = tid & 31;

    const int4 r = rois[n];
    const int yc = r.x, xc = r.y, rh = r.z, rw = r.w;
    const int roh = rh >> 1, rov = rw >> 1;

    int ymin = yc - roh; if (ymin < 0) ymin = 0;
    int ymax = yc + roh; if (ymax > Hdim) ymax = Hdim - 1;
    int xmin = xc - rov; if (xmin < 0) xmin = 0;
    int xmax = xc + rov; if (xmax > Wdim) xmax = Wdim - 1;

    const int leny = ymax - ymin;
    const int lenx = xmax - xmin;

    // stage-2 mapping: lane = ci*8 + pw  (ci = sub-channel 0..3, pw = col bin)
    const int pw = lane & 7;
    const int ci = lane >> 3;
    const int csrel = (pw * lenx) >> 3;                  // inclusive, relative to xmin
    const int cerel = ((pw + 1) * lenx + 7) >> 3;        // exclusive

    // per-warp colmax staging: [warp][sub-channel][x-rel], padded rows
    __shared__ float sh[8][4][72];

    const float NEG_INF = __int_as_float(0xff800000);

    const bool a0 = lane < lenx;
    const bool a1 = (lane + 32) < lenx;

    // this warp's 32 channels
    const float* base = fm + (size_t)(warp * 32) * PLANE + xmin + lane;

    for (int cb = 0; cb < 32; cb += 4) {
        const float* p0 = base + (size_t)cb * PLANE;
        const float* p1 = p0 + PLANE;
        const float* p2 = p1 + PLANE;
        const float* p3 = p2 + PLANE;

        #pragma unroll
        for (int ph = 0; ph < 8; ph++) {
            const int rs = ymin + ((ph * leny) >> 3);
            const int re = ymin + (((ph + 1) * leny + 7) >> 3);

            float m00 = NEG_INF, m10 = NEG_INF, m20 = NEG_INF, m30 = NEG_INF;
            float m01 = NEG_INF, m11 = NEG_INF, m21 = NEG_INF, m31 = NEG_INF;

            for (int yy = rs; yy < re; yy++) {
                const int off = yy * Wdim;
                if (a0) {
                    m00 = fmaxf(m00, __ldg(p0 + off));
                    m10 = fmaxf(m10, __ldg(p1 + off));
                    m20 = fmaxf(m20, __ldg(p2 + off));
                    m30 = fmaxf(m30, __ldg(p3 + off));
                }
                if (a1) {
                    m01 = fmaxf(m01, __ldg(p0 + off + 32));
                    m11 = fmaxf(m11, __ldg(p1 + off + 32));
                    m21 = fmaxf(m21, __ldg(p2 + off + 32));
                    m31 = fmaxf(m31, __ldg(p3 + off + 32));
                }
            }

            __syncwarp();  // prior stage-2 reads done before overwrite
            sh[warp][0][lane]      = m00;
            sh[warp][1][lane]      = m10;
            sh[warp][2][lane]      = m20;
            sh[warp][3][lane]      = m30;
            sh[warp][0][lane + 32] = m01;
            sh[warp][1][lane + 32] = m11;
            sh[warp][2][lane + 32] = m21;
            sh[warp][3][lane + 32] = m31;
            __syncwarp();

            // stage 2: each lane reduces one (sub-channel, col-bin)
            float m = NEG_INF;
            const float* s = sh[warp][ci];
            for (int j = csrel; j < cerel; j++)
                m = fmaxf(m, s[j]);

            const int c = warp * 32 + cb + ci;
            out[(((size_t)n * Cdim + c) << 6) + (ph << 3) + pw] = m;
        }
    }
}

extern "C" void kernel_launch(void* const* d_in, const int* in_sizes, int n_in,
                              void* d_out, int out_size)
{
    const float* fm   = (const float*)d_in[0];
    const int4*  rois = (const int4*)d_in[1];
    float*       out  = (float*)d_out;
    const int N = in_sizes[1] / 4;

    roi_pool_kernel<<<N, 256>>>(fm, rois, out);
}

// round 2
// speedup vs baseline: 1.9538x; 1.9538x over previous
#include <cuda_runtime.h>
#include <cstdint>

// ROI max pool, reference semantics:
//   ro = r >> 1; amin = max(a-ro, 0); amax = a+ro; if (amax > LIM) amax = LIM-1;
//   bin i: [amin + (i*len)/8, amin + ((i+1)*len+7)/8)   (empty bin -> -inf)
// feature_map: (C=256, H=64, W=64) f32, W contiguous.
// out: (N, C, 8, 8) f32.
//
// Layout: block = 128 threads (4 warps), grid = (N, 16).
// Warp w of CTA (n, by) handles channels cbase = by*16 + w*4 .. +3 for ROI n.
// Stage 1: lanes map to x (coalesced), per-lane column max over the y-bin rows,
//          4 channels in flight for ILP. Wide (lenx>32) path is loop-unswitched.
// Stage 2: staged through smem; lane = ci*8+pw reduces its x-bin.

namespace {
constexpr int Cdim  = 256;
constexpr int Wdim  = 64;
constexpr int Hdim  = 64;
constexpr int PLANE = Hdim * Wdim;  // 4096
}

template<bool WIDE>
__device__ __forceinline__
void roi_warp_work(const float* __restrict__ base,  // fm + cbase*PLANE + xmin + lane
                   float* __restrict__ shw,         // this warp's smem: [4][72]
                   float* __restrict__ outw,        // out + ((n*C + cbase) << 6)
                   int ymin, int leny, int lenx, int lane)
{
    const float NEG_INF = __int_as_float(0xff800000);
    const int pw = lane & 7;
    const int ci = lane >> 3;
    const int csrel = (pw * lenx) >> 3;
    const int cerel = ((pw + 1) * lenx + 7) >> 3;

    const bool a0 = lane < lenx;
    const bool a1 = WIDE && ((lane + 32) < lenx);

    #pragma unroll
    for (int ph = 0; ph < 8; ph++) {
        const int rs = (ph * leny) >> 3;
        const int re = ((ph + 1) * leny + 7) >> 3;

        float m00 = NEG_INF, m10 = NEG_INF, m20 = NEG_INF, m30 = NEG_INF;
        float m01 = NEG_INF, m11 = NEG_INF, m21 = NEG_INF, m31 = NEG_INF;

        const float* p = base + (size_t)(ymin + rs) * Wdim;
        for (int yy = rs; yy < re; yy++, p += Wdim) {
            if (a0) {
                m00 = fmaxf(m00, __ldg(p));
                m10 = fmaxf(m10, __ldg(p + PLANE));
                m20 = fmaxf(m20, __ldg(p + 2 * PLANE));
                m30 = fmaxf(m30, __ldg(p + 3 * PLANE));
            }
            if (WIDE) {
                if (a1) {
                    m01 = fmaxf(m01, __ldg(p + 32));
                    m11 = fmaxf(m11, __ldg(p + PLANE + 32));
                    m21 = fmaxf(m21, __ldg(p + 2 * PLANE + 32));
                    m31 = fmaxf(m31, __ldg(p + 3 * PLANE + 32));
                }
            }
        }

        __syncwarp();
        shw[0 * 72 + lane] = m00;
        shw[1 * 72 + lane] = m10;
        shw[2 * 72 + lane] = m20;
        shw[3 * 72 + lane] = m30;
        if (WIDE) {
            shw[0 * 72 + lane + 32] = m01;
            shw[1 * 72 + lane + 32] = m11;
            shw[2 * 72 + lane + 32] = m21;
            shw[3 * 72 + lane + 32] = m31;
        }
        __syncwarp();

        float m = NEG_INF;
        const float* s = shw + ci * 72;
        for (int j = csrel; j < cerel; j++)
            m = fmaxf(m, s[j]);

        // out[(ci-th channel)][ph][pw]
        outw[(ci << 6) + (ph << 3) + pw] = m;
    }
}

__global__ __launch_bounds__(128)
void roi_pool_kernel(const float* __restrict__ fm,
                     const int4* __restrict__ rois,
                     float* __restrict__ out)
{
    const int n    = blockIdx.x;
    const int tid  = threadIdx.x;
    const int warp = tid >> 5;
    const int lane = tid & 31;
    const int cbase = blockIdx.y * 16 + warp * 4;

    const int4 r = rois[n];
    const int yc = r.x, xc = r.y, rh = r.z, rw = r.w;
    const int roy = rh >> 1, rox = rw >> 1;

    int ymin = yc - roy; if (ymin < 0) ymin = 0;
    int ymax = yc + roy; if (ymax > Hdim) ymax = Hdim - 1;
    int xmin = xc - rox; if (xmin < 0) xmin = 0;
    int xmax = xc + rox; if (xmax > Wdim) xmax = Wdim - 1;

    const int leny = ymax - ymin;
    const int lenx = xmax - xmin;

    __shared__ float sh[4][4 * 72];

    const float* base = fm + (size_t)cbase * PLANE + xmin + lane;
    float* outw = out + (((size_t)n * Cdim + cbase) << 6);

    if (lenx > 32)
        roi_warp_work<true >(base, sh[warp], outw, ymin, leny, lenx, lane);
    else
        roi_warp_work<false>(base, sh[warp], outw, ymin, leny, lenx, lane);
}

extern "C" void kernel_launch(void* const* d_in, const int* in_sizes, int n_in,
                              void* d_out, int out_size)
{
    const float* fm   = (const float*)d_in[0];
    const int4*  rois = (const int4*)d_in[1];
    float*       out  = (float*)d_out;
    const int N = in_sizes[1] / 4;

    dim3 grid(N, 16);
    roi_pool_kernel<<<grid, 128>>>(fm, rois, out);
}

// round 3
// speedup vs baseline: 2.3207x; 1.1878x over previous
#include <cuda_runtime.h>
#include <cstdint>

// ROI max pool, reference semantics:
//   ro = r >> 1; amin = max(a-ro, 0); amax = a+ro; if (amax > LIM) amax = LIM-1;
//   bin i: [amin + (i*len)/8, amin + ((i+1)*len+7)/8)
// feature_map: (C=256, H=64, W=64) f32, W contiguous. out: (N, C, 8, 8) f32.
//
// block=128 (4 warps), grid=(N,16). Warp handles 4 channels of one ROI.
// Stage 1: lanes = x (coalesced LDG), column max over y-bin rows, 4-ch ILP,
//          boundary row cached to skip reloads (bins overlap by <=1 row).
// Stage 2: ping-pong smem (one __syncwarp per bin), unrolled predicated
//          6-wide reduction; lane = ci*8+pw writes out[n][c][ph][pw].

namespace {
constexpr int Cdim  = 256;
constexpr int Wdim  = 64;
constexpr int Hdim  = 64;
constexpr int PLANE = Hdim * Wdim;  // 4096
}

template<bool WIDE>
__device__ __forceinline__
void roi_warp_work(const float* __restrict__ base,  // fm + c*PLANE + ymin*W + xmin + lane
                   float* __restrict__ shw,         // this warp's smem: [2][4][72]
                   float* __restrict__ outw,        // out + ((n*C + cbase) << 6)
                   int leny, int lenx, int lane)
{
    const float NEG_INF = __int_as_float(0xff800000);
    const int pw = lane & 7;
    const int ci = lane >> 3;
    const int csrel = (pw * lenx) >> 3;
    const int width = (((pw + 1) * lenx + 7) >> 3) - csrel;   // 1..6

    const bool a0 = lane < lenx;
    const bool a1 = WIDE && ((lane + 32) < lenx);

    // boundary-row cache (narrow path only)
    float l0 = NEG_INF, l1 = NEG_INF, l2 = NEG_INF, l3 = NEG_INF;
    int prev_re = -1;

    #pragma unroll
    for (int ph = 0; ph < 8; ph++) {
        const int rs = (ph * leny) >> 3;
        const int re = ((ph + 1) * leny + 7) >> 3;

        float m0, m1, m2, m3;
        float m01 = NEG_INF, m11 = NEG_INF, m21 = NEG_INF, m31 = NEG_INF;

        int y0 = rs;
        if (!WIDE) {
            const bool seed = (rs < prev_re);        // overlap row already loaded
            m0 = seed ? l0 : NEG_INF;
            m1 = seed ? l1 : NEG_INF;
            m2 = seed ? l2 : NEG_INF;
            m3 = seed ? l3 : NEG_INF;
            y0 = seed ? rs + 1 : rs;
        } else {
            m0 = m1 = m2 = m3 = NEG_INF;
        }

        // row regs start from cache so an empty (fully-seeded) bin keeps it valid
        float v0 = l0, v1 = l1, v2 = l2, v3 = l3;

        const float* p = base + (size_t)y0 * Wdim;
        for (int yy = y0; yy < re; yy++, p += Wdim) {
            if (a0) {
                v0 = __ldg(p);
                v1 = __ldg(p + PLANE);
                v2 = __ldg(p + 2 * PLANE);
                v3 = __ldg(p + 3 * PLANE);
                m0 = fmaxf(m0, v0);
                m1 = fmaxf(m1, v1);
                m2 = fmaxf(m2, v2);
                m3 = fmaxf(m3, v3);
            }
            if (WIDE) {
                if (a1) {
                    m01 = fmaxf(m01, __ldg(p + 32));
                    m11 = fmaxf(m11, __ldg(p + PLANE + 32));
                    m21 = fmaxf(m21, __ldg(p + 2 * PLANE + 32));
                    m31 = fmaxf(m31, __ldg(p + 3 * PLANE + 32));
                }
            }
        }

        if (!WIDE) {
            l0 = v0; l1 = v1; l2 = v2; l3 = v3;
            prev_re = re;
        }

        // ---- stage 2 (ping-pong buffer: no WAR sync needed) ----
        float* sb = shw + (ph & 1) * (4 * 72);
        sb[0 * 72 + lane] = m0;
        sb[1 * 72 + lane] = m1;
        sb[2 * 72 + lane] = m2;
        sb[3 * 72 + lane] = m3;
        if (WIDE) {
            sb[0 * 72 + lane + 32] = m01;
            sb[1 * 72 + lane + 32] = m11;
            sb[2 * 72 + lane + 32] = m21;
            sb[3 * 72 + lane + 32] = m31;
        }
        __syncwarp();

        const float* s = sb + ci * 72 + csrel;
        float m = s[0];
        #pragma unroll
        for (int j = 1; j < 6; j++) {
            float v = s[j];                 // always in-bounds (csrel<=35, 35+5<72)
            if (j < width) m = fmaxf(m, v); // stale slots masked
        }

        outw[(ci << 6) + (ph << 3) + pw] = m;
        __syncwarp();   // RAW-complete before this buffer is reused at ph+2
    }
}

__global__ __launch_bounds__(128)
void roi_pool_kernel(const float* __restrict__ fm,
                     const int4* __restrict__ rois,
                     float* __restrict__ out)
{
    const int n    = blockIdx.x;
    const int tid  = threadIdx.x;
    const int warp = tid >> 5;
    const int lane = tid & 31;
    const int cbase = blockIdx.y * 16 + warp * 4;

    const int4 r = rois[n];
    const int yc = r.x, xc = r.y, rh = r.z, rw = r.w;
    const int roy = rh >> 1, rox = rw >> 1;

    int ymin = yc - roy; if (ymin < 0) ymin = 0;
    int ymax = yc + roy; if (ymax > Hdim) ymax = Hdim - 1;
    int xmin = xc - rox; if (xmin < 0) xmin = 0;
    int xmax = xc + rox; if (xmax > Wdim) xmax = Wdim - 1;

    const int leny = ymax - ymin;
    const int lenx = xmax - xmin;

    __shared__ float sh[4][2 * 4 * 72];

    const float* base = fm + (size_t)cbase * PLANE + (size_t)ymin * Wdim + xmin + lane;
    float* outw = out + (((size_t)n * Cdim + cbase) << 6);

    if (lenx > 32)
        roi_warp_work<true >(base, sh[warp], outw, leny, lenx, lane);
    else
        roi_warp_work<false>(base, sh[warp], outw, leny, lenx, lane);
}

extern "C" void kernel_launch(void* const* d_in, const int* in_sizes, int n_in,
                              void* d_out, int out_size)
{
    const float* fm   = (const float*)d_in[0];
    const int4*  rois = (const int4*)d_in[1];
    float*       out  = (float*)d_out;
    const int N = in_sizes[1] / 4;

    dim3 grid(N, 16);
    roi_pool_kernel<<<grid, 128>>>(fm, rois, out);
}